// round 1
// baseline (speedup 1.0000x reference)
#include <cuda_runtime.h>
#include <cuda_bf16.h>
#include <math.h>

// ---------------- problem constants ----------------
#define BATCH 4
#define HRES 64
#define WRES 128
#define CDIM 768
#define HEADS 8
#define HD 96
#define WIN 8
#define NTOK 64          // WIN*WIN
#define SHIFT 4
#define HID 3072
#define ROWS 32768       // BATCH*HRES*WRES
#define NWH 8            // HRES/WIN
#define NWW 16           // WRES/WIN
#define WINDOWS 512      // BATCH*NWH*NWW
#define QKVN 2304        // 3*CDIM

// ---------------- device scratch (no allocations allowed) ----------------
__device__ __align__(16) float g_x   [ROWS * CDIM];   // residual stream, pixel layout
__device__ __align__(16) float g_xw  [ROWS * CDIM];   // windowed/rolled input
__device__ __align__(16) float g_qkv [ROWS * QKVN];   // qkv in window layout
__device__ __align__(16) float g_att [ROWS * CDIM];   // attention output (window layout)
__device__ __align__(16) float g_y   [ROWS * CDIM];   // gemm output scratch
__device__ __align__(16) float g_h   [ROWS * HID];    // gated MLP hidden
__device__ float g_rpb[HEADS * NTOK * NTOK];          // relative position bias per depth
__device__ float g_qkvbias[QKVN];

// ---------------- utility copies ----------------
__global__ void copy_in_kernel(const float4* __restrict__ src) {
    int n = (ROWS * CDIM) / 4;
    for (int i = blockIdx.x * blockDim.x + threadIdx.x; i < n; i += gridDim.x * blockDim.x)
        ((float4*)g_x)[i] = src[i];
}
__global__ void copy_out_kernel(float4* __restrict__ dst) {
    int n = (ROWS * CDIM) / 4;
    for (int i = blockIdx.x * blockDim.x + threadIdx.x; i < n; i += gridDim.x * blockDim.x)
        dst[i] = ((const float4*)g_x)[i];
}

// ---------------- gather: roll(-shift) + window partition ----------------
// g_xw[(w*64+n)*C + c] = g_x[b, (wh*8+r+shift)%64, (ww*8+c8+shift)%128, c]
__global__ void gather_win_kernel(int shift) {
    int rw = blockIdx.x;                  // 0..32767 (window-token row)
    int w = rw >> 6, n = rw & 63;
    int b = w >> 7, wi = w & 127;
    int wh = wi >> 4, ww = wi & 15;
    int r = n >> 3, c = n & 7;
    int sh = (wh * 8 + r + shift) & 63;
    int sw = (ww * 8 + c + shift) & 127;
    int src = (b << 13) + sh * 128 + sw;  // pixel row
    const float4* s = (const float4*)&g_x[(size_t)src * CDIM];
    float4* d = (float4*)&g_xw[(size_t)rw * CDIM];
    d[threadIdx.x] = s[threadIdx.x];      // 192 threads * float4 = 768 floats
}

// ---------------- qkv bias: concat(q_bias, 0, v_bias) ----------------
__global__ void build_qkvbias_kernel(const float* __restrict__ qb, const float* __restrict__ vb) {
    int i = blockIdx.x * blockDim.x + threadIdx.x;
    if (i < QKVN)
        g_qkvbias[i] = (i < CDIM) ? qb[i] : ((i < 2 * CDIM) ? 0.0f : vb[i - 2 * CDIM]);
}

// ---------------- generic SGEMM: C[M,N] = A[M,K] @ B[N,K]^T + bias[N] ----------------
// 64x64 tile, BK=16, 256 threads, 4x4 per thread
__global__ void gemm_bias_kernel(const float* __restrict__ A, const float* __restrict__ Bw,
                                 const float* __restrict__ bias, float* __restrict__ C,
                                 int M, int N, int K) {
    __shared__ __align__(16) float As[16][64];
    __shared__ __align__(16) float Bs[16][64];
    int tid = threadIdx.x;
    int m0 = blockIdx.y * 64, n0 = blockIdx.x * 64;
    int lm = tid >> 2;            // 0..63
    int lk = (tid & 3) << 2;      // 0,4,8,12
    int ty = tid >> 4, tx = tid & 15;
    float acc[4][4] = {};
    for (int k0 = 0; k0 < K; k0 += 16) {
        float4 av = *(const float4*)&A [(size_t)(m0 + lm) * K + k0 + lk];
        float4 bv = *(const float4*)&Bw[(size_t)(n0 + lm) * K + k0 + lk];
        As[lk + 0][lm] = av.x; As[lk + 1][lm] = av.y; As[lk + 2][lm] = av.z; As[lk + 3][lm] = av.w;
        Bs[lk + 0][lm] = bv.x; Bs[lk + 1][lm] = bv.y; Bs[lk + 2][lm] = bv.z; Bs[lk + 3][lm] = bv.w;
        __syncthreads();
#pragma unroll
        for (int kk = 0; kk < 16; kk++) {
            float4 a = *(const float4*)&As[kk][ty << 2];
            float4 b = *(const float4*)&Bs[kk][tx << 2];
            acc[0][0] += a.x * b.x; acc[0][1] += a.x * b.y; acc[0][2] += a.x * b.z; acc[0][3] += a.x * b.w;
            acc[1][0] += a.y * b.x; acc[1][1] += a.y * b.y; acc[1][2] += a.y * b.z; acc[1][3] += a.y * b.w;
            acc[2][0] += a.z * b.x; acc[2][1] += a.z * b.y; acc[2][2] += a.z * b.z; acc[2][3] += a.z * b.w;
            acc[3][0] += a.w * b.x; acc[3][1] += a.w * b.y; acc[3][2] += a.w * b.z; acc[3][3] += a.w * b.w;
        }
        __syncthreads();
    }
#pragma unroll
    for (int i = 0; i < 4; i++) {
        int row = m0 + (ty << 2) + i;
#pragma unroll
        for (int j = 0; j < 4; j++) {
            int col = n0 + (tx << 2) + j;
            C[(size_t)row * N + col] = acc[i][j] + bias[col];
        }
    }
}

// ---------------- fc1 gated: h[:, n] = gelu(A@Wg[n]+b1[n]) * (A@Wv[n]+b1[n+HID]) ----------------
__global__ void gemm_fc1_gated_kernel(const float* __restrict__ A, const float* __restrict__ W,
                                      const float* __restrict__ b1, float* __restrict__ C,
                                      int M, int K) {
    __shared__ __align__(16) float As[16][64];
    __shared__ __align__(16) float Bg[16][64];
    __shared__ __align__(16) float Bv[16][64];
    int tid = threadIdx.x;
    int m0 = blockIdx.y * 64, n0 = blockIdx.x * 64;
    int lm = tid >> 2;
    int lk = (tid & 3) << 2;
    int ty = tid >> 4, tx = tid & 15;
    float accg[4][4] = {}, accv[4][4] = {};
    for (int k0 = 0; k0 < K; k0 += 16) {
        float4 av = *(const float4*)&A[(size_t)(m0 + lm) * K + k0 + lk];
        float4 gv = *(const float4*)&W[(size_t)(n0 + lm) * K + k0 + lk];
        float4 vv = *(const float4*)&W[(size_t)(HID + n0 + lm) * K + k0 + lk];
        As[lk + 0][lm] = av.x; As[lk + 1][lm] = av.y; As[lk + 2][lm] = av.z; As[lk + 3][lm] = av.w;
        Bg[lk + 0][lm] = gv.x; Bg[lk + 1][lm] = gv.y; Bg[lk + 2][lm] = gv.z; Bg[lk + 3][lm] = gv.w;
        Bv[lk + 0][lm] = vv.x; Bv[lk + 1][lm] = vv.y; Bv[lk + 2][lm] = vv.z; Bv[lk + 3][lm] = vv.w;
        __syncthreads();
#pragma unroll
        for (int kk = 0; kk < 16; kk++) {
            float4 a = *(const float4*)&As[kk][ty << 2];
            float4 bg = *(const float4*)&Bg[kk][tx << 2];
            float4 bv = *(const float4*)&Bv[kk][tx << 2];
            accg[0][0] += a.x * bg.x; accg[0][1] += a.x * bg.y; accg[0][2] += a.x * bg.z; accg[0][3] += a.x * bg.w;
            accg[1][0] += a.y * bg.x; accg[1][1] += a.y * bg.y; accg[1][2] += a.y * bg.z; accg[1][3] += a.y * bg.w;
            accg[2][0] += a.z * bg.x; accg[2][1] += a.z * bg.y; accg[2][2] += a.z * bg.z; accg[2][3] += a.z * bg.w;
            accg[3][0] += a.w * bg.x; accg[3][1] += a.w * bg.y; accg[3][2] += a.w * bg.z; accg[3][3] += a.w * bg.w;
            accv[0][0] += a.x * bv.x; accv[0][1] += a.x * bv.y; accv[0][2] += a.x * bv.z; accv[0][3] += a.x * bv.w;
            accv[1][0] += a.y * bv.x; accv[1][1] += a.y * bv.y; accv[1][2] += a.y * bv.z; accv[1][3] += a.y * bv.w;
            accv[2][0] += a.z * bv.x; accv[2][1] += a.z * bv.y; accv[2][2] += a.z * bv.z; accv[2][3] += a.z * bv.w;
            accv[3][0] += a.w * bv.x; accv[3][1] += a.w * bv.y; accv[3][2] += a.w * bv.z; accv[3][3] += a.w * bv.w;
        }
        __syncthreads();
    }
#pragma unroll
    for (int i = 0; i < 4; i++) {
        int row = m0 + (ty << 2) + i;
#pragma unroll
        for (int j = 0; j < 4; j++) {
            int col = n0 + (tx << 2) + j;
            float gate = accg[i][j] + b1[col];
            float val  = accv[i][j] + b1[HID + col];
            float gl = 0.5f * gate * (1.0f + erff(gate * 0.70710678118654752f));
            C[(size_t)row * HID + col] = gl * val;
        }
    }
}

// ---------------- q/k L2 normalization in-place (one warp per 96-vector) ----------------
__global__ void norm_qk_kernel() {
    int v = blockIdx.x * 8 + (threadIdx.x >> 5);   // vector id 0 .. 32768*16-1
    int lane = threadIdx.x & 31;
    int token = v >> 4;
    int rest = v & 15;
    int hh = rest >> 1;
    int isK = rest & 1;
    float* base = &g_qkv[(size_t)token * QKVN + isK * CDIM + hh * HD];
    float x0 = base[lane], x1 = base[lane + 32], x2 = base[lane + 64];
    float s = x0 * x0 + x1 * x1 + x2 * x2;
#pragma unroll
    for (int o = 16; o; o >>= 1) s += __shfl_xor_sync(0xffffffffu, s, o);
    float inv = 1.0f / fmaxf(sqrtf(s), 1e-12f);
    base[lane] = x0 * inv; base[lane + 32] = x1 * inv; base[lane + 64] = x2 * inv;
}

// ---------------- continuous relative position bias ----------------
__device__ __forceinline__ float coordval(int a) {
    float v = (float)(a - 7) * (8.0f / 7.0f);
    float f = log2f(fabsf(v) + 1.0f) * (1.0f / 3.0f);  // /log2(8)
    return copysignf(f, v);
}
__global__ void rpb_kernel(const float* __restrict__ w1, const float* __restrict__ b1,
                           const float* __restrict__ w2) {
    __shared__ float tbl[225][8];
    int tid = threadIdx.x;
    if (tid < 225) {
        int a = tid / 15, b_ = tid % 15;
        float c0 = coordval(a), c1 = coordval(b_);
        float acc[8] = {0, 0, 0, 0, 0, 0, 0, 0};
        for (int k = 0; k < 512; k++) {
            float hid = fmaxf(c0 * w1[k * 2 + 0] + c1 * w1[k * 2 + 1] + b1[k], 0.0f);
#pragma unroll
            for (int h = 0; h < 8; h++) acc[h] += hid * w2[h * 512 + k];
        }
#pragma unroll
        for (int h = 0; h < 8; h++) tbl[tid][h] = acc[h];
    }
    __syncthreads();
    for (int e = tid; e < HEADS * NTOK * NTOK; e += 256) {
        int h = e >> 12;
        int ij = e & 4095;
        int i = ij >> 6, j = ij & 63;
        int dy = (i >> 3) - (j >> 3) + 7;
        int dx = (i & 7) - (j & 7) + 7;
        float t = tbl[dy * 15 + dx][h];
        g_rpb[e] = 16.0f / (1.0f + expf(-t));
    }
}

// ---------------- attention: per (window, head) ----------------
__global__ void attn_kernel(const float* __restrict__ logit_scale, int shift) {
    int w = blockIdx.x;   // 0..511
    int h = blockIdx.y;   // 0..7
    __shared__ float kn[64][97];   // padded vs 96 to kill LDS bank conflicts
    __shared__ float at[64][65];
    int tid = threadIdx.x;         // 256

    for (int e = tid; e < 64 * HD; e += 256) {
        int j = e / HD, dd = e % HD;
        kn[j][dd] = g_qkv[(size_t)(w * 64 + j) * QKVN + CDIM + h * HD + dd];
    }
    float scale = expf(fminf(logit_scale[h], 4.605170186f));  // ln(100)
    int wimg = w & 127;
    int wh = wimg >> 4, ww = wimg & 15;
    __syncthreads();

    for (int e = tid; e < 4096; e += 256) {
        int i = e >> 6, j = e & 63;
        const float* qrow = &g_qkv[(size_t)(w * 64 + i) * QKVN + h * HD];
        float s = 0.0f;
#pragma unroll 8
        for (int dd = 0; dd < HD; dd++) s += qrow[dd] * kn[j][dd];
        float val = scale * s + g_rpb[h * 4096 + i * 64 + j];
        if (shift) {
            int gir = wh * 8 + (i >> 3), gic = ww * 8 + (i & 7);
            int gjr = wh * 8 + (j >> 3), gjc = ww * 8 + (j & 7);
            int idi = (gir < 56 ? 0 : (gir < 60 ? 1 : 2)) * 3 + (gic < 120 ? 0 : (gic < 124 ? 1 : 2));
            int idj = (gjr < 56 ? 0 : (gjr < 60 ? 1 : 2)) * 3 + (gjc < 120 ? 0 : (gjc < 124 ? 1 : 2));
            if (idi != idj) val -= 100.0f;
        }
        at[i][j] = val;
    }
    __syncthreads();

    if (tid < 64) {
        float mx = -1e30f;
        for (int j = 0; j < 64; j++) mx = fmaxf(mx, at[tid][j]);
        float sum = 0.0f;
        for (int j = 0; j < 64; j++) { float ev = expf(at[tid][j] - mx); at[tid][j] = ev; sum += ev; }
        float inv = 1.0f / sum;
        for (int j = 0; j < 64; j++) at[tid][j] *= inv;
    }
    __syncthreads();

    for (int e = tid; e < 64 * HD; e += 256) {
        int i = e / HD, dd = e % HD;
        float s = 0.0f;
#pragma unroll 8
        for (int m = 0; m < 64; m++)
            s += at[i][m] * g_qkv[(size_t)(w * 64 + m) * QKVN + 2 * CDIM + h * HD + dd];
        g_att[(size_t)(w * 64 + i) * CDIM + h * HD + dd] = s;
    }
}

// ---------------- LN + residual (optionally un-window + un-shift) ----------------
__global__ void ln_add_kernel(const float* __restrict__ y, const float* __restrict__ g,
                              const float* __restrict__ b, int windowed, int shift) {
    int prow = blockIdx.x;   // pixel row
    int src;
    if (windowed) {
        int bb = prow >> 13;
        int p = (prow >> 7) & 63;
        int q = prow & 127;
        int i = (p - shift + 64) & 63;
        int j = (q - shift + 128) & 127;
        src = (bb * 128 + (i >> 3) * 16 + (j >> 3)) * 64 + (i & 7) * 8 + (j & 7);
    } else {
        src = prow;
    }
    int tid = threadIdx.x;   // 256
    const float* yr = &y[(size_t)src * CDIM];
    float v0 = yr[tid], v1 = yr[tid + 256], v2 = yr[tid + 512];
    __shared__ float red[256];
    red[tid] = v0 + v1 + v2;
    __syncthreads();
    for (int o = 128; o; o >>= 1) { if (tid < o) red[tid] += red[tid + o]; __syncthreads(); }
    float mu = red[0] * (1.0f / CDIM);
    __syncthreads();
    float d0 = v0 - mu, d1 = v1 - mu, d2 = v2 - mu;
    red[tid] = d0 * d0 + d1 * d1 + d2 * d2;
    __syncthreads();
    for (int o = 128; o; o >>= 1) { if (tid < o) red[tid] += red[tid + o]; __syncthreads(); }
    float rstd = rsqrtf(red[0] * (1.0f / CDIM) + 1e-5f);
    float* xr = &g_x[(size_t)prow * CDIM];
    xr[tid]       += d0 * rstd * g[tid]       + b[tid];
    xr[tid + 256] += d1 * rstd * g[tid + 256] + b[tid + 256];
    xr[tid + 512] += d2 * rstd * g[tid + 512] + b[tid + 512];
}

// ---------------- host launch ----------------
extern "C" void kernel_launch(void* const* d_in, const int* in_sizes, int n_in,
                              void* d_out, int out_size) {
    const float* x_in       = (const float*)d_in[0];
    const float* norm1_g    = (const float*)d_in[1];
    const float* norm1_b    = (const float*)d_in[2];
    const float* norm2_g    = (const float*)d_in[3];
    const float* norm2_b    = (const float*)d_in[4];
    const float* qkv_w      = (const float*)d_in[5];
    const float* q_bias     = (const float*)d_in[6];
    const float* v_bias     = (const float*)d_in[7];
    const float* logit_scale= (const float*)d_in[8];
    const float* cpb_w1     = (const float*)d_in[9];
    const float* cpb_b1     = (const float*)d_in[10];
    const float* cpb_w2     = (const float*)d_in[11];
    const float* proj_w     = (const float*)d_in[12];
    const float* proj_b     = (const float*)d_in[13];
    const float* fc1_w      = (const float*)d_in[14];
    const float* fc1_b      = (const float*)d_in[15];
    const float* fc2_w      = (const float*)d_in[16];
    const float* fc2_b      = (const float*)d_in[17];

    float *pxw, *pqkv, *patt, *py, *ph, *px;
    cudaGetSymbolAddress((void**)&px,   g_x);
    cudaGetSymbolAddress((void**)&pxw,  g_xw);
    cudaGetSymbolAddress((void**)&pqkv, g_qkv);
    cudaGetSymbolAddress((void**)&patt, g_att);
    cudaGetSymbolAddress((void**)&py,   g_y);
    cudaGetSymbolAddress((void**)&ph,   g_h);
    (void)px;

    copy_in_kernel<<<4096, 256>>>((const float4*)x_in);

    for (int d = 0; d < 2; d++) {
        int shift = (d & 1) ? SHIFT : 0;

        gather_win_kernel<<<ROWS, 192>>>(shift);
        build_qkvbias_kernel<<<9, 256>>>(q_bias + d * CDIM, v_bias + d * CDIM);

        {   // qkv gemm: 32768 x 2304 x 768
            float* pqb; cudaGetSymbolAddress((void**)&pqb, g_qkvbias);
            dim3 grid(QKVN / 64, ROWS / 64);
            gemm_bias_kernel<<<grid, 256>>>(pxw, qkv_w + (size_t)d * QKVN * CDIM, pqb, pqkv,
                                            ROWS, QKVN, CDIM);
        }
        norm_qk_kernel<<<ROWS * 16 / 8, 256>>>();
        rpb_kernel<<<1, 256>>>(cpb_w1 + d * 512 * 2, cpb_b1 + d * 512, cpb_w2 + d * 8 * 512);

        {   // attention
            dim3 grid(WINDOWS, HEADS);
            attn_kernel<<<grid, 256>>>(logit_scale + d * HEADS, shift);
        }
        {   // proj gemm: 32768 x 768 x 768
            dim3 grid(CDIM / 64, ROWS / 64);
            gemm_bias_kernel<<<grid, 256>>>(patt, proj_w + (size_t)d * CDIM * CDIM,
                                            proj_b + d * CDIM, py, ROWS, CDIM, CDIM);
        }
        ln_add_kernel<<<ROWS, 256>>>(py, norm1_g + d * CDIM, norm1_b + d * CDIM, 1, shift);

        {   // fc1 gated: 32768 x 3072 (x2 dots) x 768
            dim3 grid(HID / 64, ROWS / 64);
            gemm_fc1_gated_kernel<<<grid, 256>>>(px, fc1_w + (size_t)d * 2 * HID * CDIM,
                                                 fc1_b + (size_t)d * 2 * HID, ph, ROWS, CDIM);
        }
        {   // fc2: 32768 x 768 x 3072
            dim3 grid(CDIM / 64, ROWS / 64);
            gemm_bias_kernel<<<grid, 256>>>(ph, fc2_w + (size_t)d * CDIM * HID,
                                            fc2_b + d * CDIM, py, ROWS, CDIM, HID);
        }
        ln_add_kernel<<<ROWS, 256>>>(py, norm2_g + d * CDIM, norm2_b + d * CDIM, 0, 0);
    }

    copy_out_kernel<<<4096, 256>>>((float4*)d_out);
}

// round 2
// speedup vs baseline: 2.8772x; 2.8772x over previous
#include <cuda_runtime.h>
#include <cuda_bf16.h>
#include <math.h>

// ---------------- problem constants ----------------
#define BATCH 4
#define HRES 64
#define WRES 128
#define CDIM 768
#define HEADS 8
#define HD 96
#define WIN 8
#define NTOK 64
#define SHIFT 4
#define HID 3072
#define ROWS 32768
#define WINDOWS 512
#define QKVN 2304

// ---------------- device scratch ----------------
__device__ __align__(16) float g_x   [ROWS * CDIM];
__device__ __align__(16) float g_xw  [ROWS * CDIM];
__device__ __align__(16) float g_qkv [ROWS * QKVN];
__device__ __align__(16) float g_att [ROWS * CDIM];
__device__ __align__(16) float g_y   [ROWS * CDIM];
__device__ __align__(16) float g_h   [ROWS * HID];       // gated hidden
__device__ __align__(16) float g_h2  [ROWS * 2 * HID];   // raw fc1 output
__device__ float g_rpb[HEADS * NTOK * NTOK];
__device__ float g_qkvbias[QKVN];

// ---------------- utility copies ----------------
__global__ void copy_in_kernel(const float4* __restrict__ src) {
    int n = (ROWS * CDIM) / 4;
    for (int i = blockIdx.x * blockDim.x + threadIdx.x; i < n; i += gridDim.x * blockDim.x)
        ((float4*)g_x)[i] = src[i];
}
__global__ void copy_out_kernel(float4* __restrict__ dst) {
    int n = (ROWS * CDIM) / 4;
    for (int i = blockIdx.x * blockDim.x + threadIdx.x; i < n; i += gridDim.x * blockDim.x)
        dst[i] = ((const float4*)g_x)[i];
}

// ---------------- gather: roll(-shift) + window partition ----------------
__global__ void gather_win_kernel(int shift) {
    int rw = blockIdx.x;
    int w = rw >> 6, n = rw & 63;
    int b = w >> 7, wi = w & 127;
    int wh = wi >> 4, ww = wi & 15;
    int r = n >> 3, c = n & 7;
    int sh = (wh * 8 + r + shift) & 63;
    int sw = (ww * 8 + c + shift) & 127;
    int src = (b << 13) + sh * 128 + sw;
    const float4* s = (const float4*)&g_x[(size_t)src * CDIM];
    float4* d = (float4*)&g_xw[(size_t)rw * CDIM];
    d[threadIdx.x] = s[threadIdx.x];
}

__global__ void build_qkvbias_kernel(const float* __restrict__ qb, const float* __restrict__ vb) {
    int i = blockIdx.x * blockDim.x + threadIdx.x;
    if (i < QKVN)
        g_qkvbias[i] = (i < CDIM) ? qb[i] : ((i < 2 * CDIM) ? 0.0f : vb[i - 2 * CDIM]);
}

// ---------------- tf32 tensor-core GEMM: C[M,N] = A[M,K] @ B[N,K]^T + bias ----------------
// 128x128 block, BK=16, 256 threads (8 warps, 32x64 warp tiles), double-buffered smem.
#define PITCH 20

__device__ __forceinline__ unsigned f2tf(float x) {
    unsigned r; asm("cvt.rna.tf32.f32 %0, %1;" : "=r"(r) : "f"(x)); return r;
}
__device__ __forceinline__ void mma_tf32(float* c, unsigned a0, unsigned a1, unsigned a2,
                                         unsigned a3, unsigned b0, unsigned b1) {
    asm volatile(
        "mma.sync.aligned.m16n8k8.row.col.f32.tf32.tf32.f32 "
        "{%0,%1,%2,%3}, {%4,%5,%6,%7}, {%8,%9}, {%0,%1,%2,%3};"
        : "+f"(c[0]), "+f"(c[1]), "+f"(c[2]), "+f"(c[3])
        : "r"(a0), "r"(a1), "r"(a2), "r"(a3), "r"(b0), "r"(b1));
}

__global__ __launch_bounds__(256, 2) void gemm_tf32_kernel(
    const float* __restrict__ A, const float* __restrict__ Bw,
    const float* __restrict__ bias, float* __restrict__ C,
    int M, int N, int K) {
    __shared__ unsigned As[2][128][PITCH];
    __shared__ unsigned Bs[2][128][PITCH];
    int tid = threadIdx.x;
    int wid = tid >> 5, lane = tid & 31;
    int g = lane >> 2, tg = lane & 3;
    int wm = wid & 3, wn = wid >> 2;   // warp tile: rows wm*32, cols wn*64
    int m0 = blockIdx.y * 128, n0 = blockIdx.x * 128;

    float acc[2][8][4];
#pragma unroll
    for (int i = 0; i < 2; i++)
#pragma unroll
        for (int j = 0; j < 8; j++)
#pragma unroll
            for (int l = 0; l < 4; l++) acc[i][j][l] = 0.0f;

    // prologue: stage 0
    {
#pragma unroll
        for (int j = 0; j < 2; j++) {
            int idx = tid + 256 * j;
            int row = idx >> 2, kq = (idx & 3) << 2;
            float4 a = *(const float4*)&A [(size_t)(m0 + row) * K + kq];
            float4 b = *(const float4*)&Bw[(size_t)(n0 + row) * K + kq];
            As[0][row][kq + 0] = f2tf(a.x); As[0][row][kq + 1] = f2tf(a.y);
            As[0][row][kq + 2] = f2tf(a.z); As[0][row][kq + 3] = f2tf(a.w);
            Bs[0][row][kq + 0] = f2tf(b.x); Bs[0][row][kq + 1] = f2tf(b.y);
            Bs[0][row][kq + 2] = f2tf(b.z); Bs[0][row][kq + 3] = f2tf(b.w);
        }
    }
    __syncthreads();

    int nk = K >> 4;
    int buf = 0;
    for (int kt = 0; kt < nk; kt++) {
        float4 ra[2], rb[2];
        int have_next = (kt + 1 < nk);
        if (have_next) {
            int k0 = (kt + 1) << 4;
#pragma unroll
            for (int j = 0; j < 2; j++) {
                int idx = tid + 256 * j;
                int row = idx >> 2, kq = (idx & 3) << 2;
                ra[j] = *(const float4*)&A [(size_t)(m0 + row) * K + k0 + kq];
                rb[j] = *(const float4*)&Bw[(size_t)(n0 + row) * K + k0 + kq];
            }
        }
        // compute on buf
#pragma unroll
        for (int ko = 0; ko < 16; ko += 8) {
            unsigned bf[8][2];
#pragma unroll
            for (int nf = 0; nf < 8; nf++) {
                int n = wn * 64 + nf * 8 + g;
                bf[nf][0] = Bs[buf][n][ko + tg];
                bf[nf][1] = Bs[buf][n][ko + tg + 4];
            }
#pragma unroll
            for (int mf = 0; mf < 2; mf++) {
                int m = wm * 32 + mf * 16 + g;
                unsigned a0 = As[buf][m][ko + tg];
                unsigned a1 = As[buf][m + 8][ko + tg];
                unsigned a2 = As[buf][m][ko + tg + 4];
                unsigned a3 = As[buf][m + 8][ko + tg + 4];
#pragma unroll
                for (int nf = 0; nf < 8; nf++)
                    mma_tf32(acc[mf][nf], a0, a1, a2, a3, bf[nf][0], bf[nf][1]);
            }
        }
        if (have_next) {
            int ob = buf ^ 1;
#pragma unroll
            for (int j = 0; j < 2; j++) {
                int idx = tid + 256 * j;
                int row = idx >> 2, kq = (idx & 3) << 2;
                As[ob][row][kq + 0] = f2tf(ra[j].x); As[ob][row][kq + 1] = f2tf(ra[j].y);
                As[ob][row][kq + 2] = f2tf(ra[j].z); As[ob][row][kq + 3] = f2tf(ra[j].w);
                Bs[ob][row][kq + 0] = f2tf(rb[j].x); Bs[ob][row][kq + 1] = f2tf(rb[j].y);
                Bs[ob][row][kq + 2] = f2tf(rb[j].z); Bs[ob][row][kq + 3] = f2tf(rb[j].w);
            }
        }
        __syncthreads();
        buf ^= 1;
    }

    // epilogue
#pragma unroll
    for (int mf = 0; mf < 2; mf++) {
#pragma unroll
        for (int nf = 0; nf < 8; nf++) {
            int r = m0 + wm * 32 + mf * 16 + g;
            int cb = n0 + wn * 64 + nf * 8 + 2 * tg;
            float b0 = bias[cb], b1 = bias[cb + 1];
            float2 v0 = make_float2(acc[mf][nf][0] + b0, acc[mf][nf][1] + b1);
            float2 v1 = make_float2(acc[mf][nf][2] + b0, acc[mf][nf][3] + b1);
            *(float2*)&C[(size_t)r * N + cb] = v0;
            *(float2*)&C[(size_t)(r + 8) * N + cb] = v1;
        }
    }
}

// ---------------- gated GELU elementwise ----------------
__global__ void gated_gelu_kernel() {
    int n = ROWS * HID / 4;
    for (int i = blockIdx.x * blockDim.x + threadIdx.x; i < n; i += gridDim.x * blockDim.x) {
        int row = i / (HID / 4);
        int col4 = i % (HID / 4);
        float4 gt = *(const float4*)&g_h2[(size_t)row * 2 * HID + col4 * 4];
        float4 vl = *(const float4*)&g_h2[(size_t)row * 2 * HID + HID + col4 * 4];
        float4 o;
        o.x = 0.5f * gt.x * (1.0f + erff(gt.x * 0.70710678118654752f)) * vl.x;
        o.y = 0.5f * gt.y * (1.0f + erff(gt.y * 0.70710678118654752f)) * vl.y;
        o.z = 0.5f * gt.z * (1.0f + erff(gt.z * 0.70710678118654752f)) * vl.z;
        o.w = 0.5f * gt.w * (1.0f + erff(gt.w * 0.70710678118654752f)) * vl.w;
        *(float4*)&g_h[(size_t)row * HID + col4 * 4] = o;
    }
}

// ---------------- q/k L2 normalization ----------------
__global__ void norm_qk_kernel() {
    int v = blockIdx.x * 8 + (threadIdx.x >> 5);
    int lane = threadIdx.x & 31;
    int token = v >> 4;
    int rest = v & 15;
    int hh = rest >> 1;
    int isK = rest & 1;
    float* base = &g_qkv[(size_t)token * QKVN + isK * CDIM + hh * HD];
    float x0 = base[lane], x1 = base[lane + 32], x2 = base[lane + 64];
    float s = x0 * x0 + x1 * x1 + x2 * x2;
#pragma unroll
    for (int o = 16; o; o >>= 1) s += __shfl_xor_sync(0xffffffffu, s, o);
    float inv = 1.0f / fmaxf(sqrtf(s), 1e-12f);
    base[lane] = x0 * inv; base[lane + 32] = x1 * inv; base[lane + 64] = x2 * inv;
}

// ---------------- continuous relative position bias ----------------
__device__ __forceinline__ float coordval(int a) {
    float v = (float)(a - 7) * (8.0f / 7.0f);
    float f = log2f(fabsf(v) + 1.0f) * (1.0f / 3.0f);
    return copysignf(f, v);
}
__global__ void rpb_kernel(const float* __restrict__ w1, const float* __restrict__ b1,
                           const float* __restrict__ w2) {
    __shared__ float tbl[225][8];
    int tid = threadIdx.x;
    if (tid < 225) {
        int a = tid / 15, b_ = tid % 15;
        float c0 = coordval(a), c1 = coordval(b_);
        float acc[8] = {0, 0, 0, 0, 0, 0, 0, 0};
        for (int k = 0; k < 512; k++) {
            float hid = fmaxf(c0 * w1[k * 2 + 0] + c1 * w1[k * 2 + 1] + b1[k], 0.0f);
#pragma unroll
            for (int h = 0; h < 8; h++) acc[h] += hid * w2[h * 512 + k];
        }
#pragma unroll
        for (int h = 0; h < 8; h++) tbl[tid][h] = acc[h];
    }
    __syncthreads();
    for (int e = tid; e < HEADS * NTOK * NTOK; e += 256) {
        int h = e >> 12;
        int ij = e & 4095;
        int i = ij >> 6, j = ij & 63;
        int dy = (i >> 3) - (j >> 3) + 7;
        int dx = (i & 7) - (j & 7) + 7;
        float t = tbl[dy * 15 + dx][h];
        g_rpb[e] = 16.0f / (1.0f + expf(-t));
    }
}

// ---------------- attention per (window, head) ----------------
__global__ void attn_kernel(const float* __restrict__ logit_scale, int shift) {
    int w = blockIdx.x;
    int h = blockIdx.y;
    __shared__ float kn[64][97];
    __shared__ float at[64][65];
    int tid = threadIdx.x;

    for (int e = tid; e < 64 * HD; e += 256) {
        int j = e / HD, dd = e % HD;
        kn[j][dd] = g_qkv[(size_t)(w * 64 + j) * QKVN + CDIM + h * HD + dd];
    }
    float scale = expf(fminf(logit_scale[h], 4.605170186f));
    int wimg = w & 127;
    int wh = wimg >> 4, ww = wimg & 15;
    __syncthreads();

    for (int e = tid; e < 4096; e += 256) {
        int i = e >> 6, j = e & 63;
        const float* qrow = &g_qkv[(size_t)(w * 64 + i) * QKVN + h * HD];
        float s = 0.0f;
#pragma unroll 8
        for (int dd = 0; dd < HD; dd++) s += qrow[dd] * kn[j][dd];
        float val = scale * s + g_rpb[h * 4096 + i * 64 + j];
        if (shift) {
            int gir = wh * 8 + (i >> 3), gic = ww * 8 + (i & 7);
            int gjr = wh * 8 + (j >> 3), gjc = ww * 8 + (j & 7);
            int idi = (gir < 56 ? 0 : (gir < 60 ? 1 : 2)) * 3 + (gic < 120 ? 0 : (gic < 124 ? 1 : 2));
            int idj = (gjr < 56 ? 0 : (gjr < 60 ? 1 : 2)) * 3 + (gjc < 120 ? 0 : (gjc < 124 ? 1 : 2));
            if (idi != idj) val -= 100.0f;
        }
        at[i][j] = val;
    }
    __syncthreads();

    if (tid < 64) {
        float mx = -1e30f;
        for (int j = 0; j < 64; j++) mx = fmaxf(mx, at[tid][j]);
        float sum = 0.0f;
        for (int j = 0; j < 64; j++) { float ev = expf(at[tid][j] - mx); at[tid][j] = ev; sum += ev; }
        float inv = 1.0f / sum;
        for (int j = 0; j < 64; j++) at[tid][j] *= inv;
    }
    __syncthreads();

    for (int e = tid; e < 64 * HD; e += 256) {
        int i = e / HD, dd = e % HD;
        float s = 0.0f;
#pragma unroll 8
        for (int m = 0; m < 64; m++)
            s += at[i][m] * g_qkv[(size_t)(w * 64 + m) * QKVN + 2 * CDIM + h * HD + dd];
        g_att[(size_t)(w * 64 + i) * CDIM + h * HD + dd] = s;
    }
}

// ---------------- LN + residual ----------------
__global__ void ln_add_kernel(const float* __restrict__ y, const float* __restrict__ g,
                              const float* __restrict__ b, int windowed, int shift) {
    int prow = blockIdx.x;
    int src;
    if (windowed) {
        int bb = prow >> 13;
        int p = (prow >> 7) & 63;
        int q = prow & 127;
        int i = (p - shift + 64) & 63;
        int j = (q - shift + 128) & 127;
        src = (bb * 128 + (i >> 3) * 16 + (j >> 3)) * 64 + (i & 7) * 8 + (j & 7);
    } else {
        src = prow;
    }
    int tid = threadIdx.x;
    const float* yr = &y[(size_t)src * CDIM];
    float v0 = yr[tid], v1 = yr[tid + 256], v2 = yr[tid + 512];
    __shared__ float red[256];
    red[tid] = v0 + v1 + v2;
    __syncthreads();
    for (int o = 128; o; o >>= 1) { if (tid < o) red[tid] += red[tid + o]; __syncthreads(); }
    float mu = red[0] * (1.0f / CDIM);
    __syncthreads();
    float d0 = v0 - mu, d1 = v1 - mu, d2 = v2 - mu;
    red[tid] = d0 * d0 + d1 * d1 + d2 * d2;
    __syncthreads();
    for (int o = 128; o; o >>= 1) { if (tid < o) red[tid] += red[tid + o]; __syncthreads(); }
    float rstd = rsqrtf(red[0] * (1.0f / CDIM) + 1e-5f);
    float* xr = &g_x[(size_t)prow * CDIM];
    xr[tid]       += d0 * rstd * g[tid]       + b[tid];
    xr[tid + 256] += d1 * rstd * g[tid + 256] + b[tid + 256];
    xr[tid + 512] += d2 * rstd * g[tid + 512] + b[tid + 512];
}

// ---------------- host launch ----------------
extern "C" void kernel_launch(void* const* d_in, const int* in_sizes, int n_in,
                              void* d_out, int out_size) {
    const float* x_in       = (const float*)d_in[0];
    const float* norm1_g    = (const float*)d_in[1];
    const float* norm1_b    = (const float*)d_in[2];
    const float* norm2_g    = (const float*)d_in[3];
    const float* norm2_b    = (const float*)d_in[4];
    const float* qkv_w      = (const float*)d_in[5];
    const float* q_bias     = (const float*)d_in[6];
    const float* v_bias     = (const float*)d_in[7];
    const float* logit_scale= (const float*)d_in[8];
    const float* cpb_w1     = (const float*)d_in[9];
    const float* cpb_b1     = (const float*)d_in[10];
    const float* cpb_w2     = (const float*)d_in[11];
    const float* proj_w     = (const float*)d_in[12];
    const float* proj_b     = (const float*)d_in[13];
    const float* fc1_w      = (const float*)d_in[14];
    const float* fc1_b      = (const float*)d_in[15];
    const float* fc2_w      = (const float*)d_in[16];
    const float* fc2_b      = (const float*)d_in[17];

    float *px, *pxw, *pqkv, *patt, *py, *ph, *ph2, *pqb;
    cudaGetSymbolAddress((void**)&px,   g_x);
    cudaGetSymbolAddress((void**)&pxw,  g_xw);
    cudaGetSymbolAddress((void**)&pqkv, g_qkv);
    cudaGetSymbolAddress((void**)&patt, g_att);
    cudaGetSymbolAddress((void**)&py,   g_y);
    cudaGetSymbolAddress((void**)&ph,   g_h);
    cudaGetSymbolAddress((void**)&ph2,  g_h2);
    cudaGetSymbolAddress((void**)&pqb,  g_qkvbias);

    copy_in_kernel<<<4096, 256>>>((const float4*)x_in);

    for (int d = 0; d < 2; d++) {
        int shift = (d & 1) ? SHIFT : 0;

        gather_win_kernel<<<ROWS, 192>>>(shift);
        build_qkvbias_kernel<<<9, 256>>>(q_bias + d * CDIM, v_bias + d * CDIM);

        {   // qkv: 32768 x 2304 x 768
            dim3 grid(QKVN / 128, ROWS / 128);
            gemm_tf32_kernel<<<grid, 256>>>(pxw, qkv_w + (size_t)d * QKVN * CDIM, pqb, pqkv,
                                            ROWS, QKVN, CDIM);
        }
        norm_qk_kernel<<<ROWS * 16 / 8, 256>>>();
        rpb_kernel<<<1, 256>>>(cpb_w1 + d * 512 * 2, cpb_b1 + d * 512, cpb_w2 + d * 8 * 512);

        {   // attention
            dim3 grid(WINDOWS, HEADS);
            attn_kernel<<<grid, 256>>>(logit_scale + d * HEADS, shift);
        }
        {   // proj: 32768 x 768 x 768
            dim3 grid(CDIM / 128, ROWS / 128);
            gemm_tf32_kernel<<<grid, 256>>>(patt, proj_w + (size_t)d * CDIM * CDIM,
                                            proj_b + d * CDIM, py, ROWS, CDIM, CDIM);
        }
        ln_add_kernel<<<ROWS, 256>>>(py, norm1_g + d * CDIM, norm1_b + d * CDIM, 1, shift);

        {   // fc1 raw: 32768 x 6144 x 768
            dim3 grid(2 * HID / 128, ROWS / 128);
            gemm_tf32_kernel<<<grid, 256>>>(px, fc1_w + (size_t)d * 2 * HID * CDIM,
                                            fc1_b + (size_t)d * 2 * HID, ph2, ROWS, 2 * HID, CDIM);
        }
        gated_gelu_kernel<<<16384, 256>>>();
        {   // fc2: 32768 x 768 x 3072
            dim3 grid(CDIM / 128, ROWS / 128);
            gemm_tf32_kernel<<<grid, 256>>>(ph, fc2_w + (size_t)d * CDIM * HID,
                                            fc2_b + d * CDIM, py, ROWS, CDIM, HID);
        }
        ln_add_kernel<<<ROWS, 256>>>(py, norm2_g + d * CDIM, norm2_b + d * CDIM, 0, 0);
    }

    copy_out_kernel<<<4096, 256>>>((float4*)d_out);
}

// round 7
// speedup vs baseline: 3.3886x; 1.1777x over previous
#include <cuda_runtime.h>
#include <cuda_bf16.h>
#include <math.h>

// ---------------- problem constants ----------------
#define CDIM 768
#define HEADS 8
#define HD 96
#define NTOK 64
#define SHIFT 4
#define HID 3072
#define ROWS 32768
#define WINDOWS 512
#define QKVN 2304

// ---------------- device scratch ----------------
__device__ __align__(16) float g_x   [ROWS * CDIM];
__device__ __align__(16) float g_xr  [ROWS * CDIM];   // tf32-rounded residual (fc1 A)
__device__ __align__(16) float g_xw  [ROWS * CDIM];   // rounded windowed input
__device__ __align__(16) float g_qkv [ROWS * QKVN];
__device__ __align__(16) float g_att [ROWS * CDIM];   // rounded attention output
__device__ __align__(16) float g_y   [ROWS * CDIM];
__device__ __align__(16) float g_h   [ROWS * HID];    // rounded gated hidden
__device__ __align__(16) float g_wqkv[QKVN * CDIM];   // rounded weights (per depth)
__device__ __align__(16) float g_wproj[CDIM * CDIM];
__device__ __align__(16) float g_wfc1[2 * HID * CDIM];// interleaved gate/val rows
__device__ __align__(16) float g_wfc2[CDIM * HID];
__device__ float g_bfc1[2 * HID];
__device__ float g_rpb[HEADS * NTOK * NTOK];
__device__ float g_qkvbias[QKVN];

__device__ __forceinline__ unsigned f2tf(float x) {
    unsigned r; asm("cvt.rna.tf32.f32 %0, %1;" : "=r"(r) : "f"(x)); return r;
}
__device__ __forceinline__ float f2tff(float x) { return __uint_as_float(f2tf(x)); }

// ---------------- utility copies ----------------
__global__ void copy_in_kernel(const float4* __restrict__ src) {
    int n = (ROWS * CDIM) / 4;
    for (int i = blockIdx.x * blockDim.x + threadIdx.x; i < n; i += gridDim.x * blockDim.x)
        ((float4*)g_x)[i] = src[i];
}
__global__ void copy_out_kernel(float4* __restrict__ dst) {
    int n = (ROWS * CDIM) / 4;
    for (int i = blockIdx.x * blockDim.x + threadIdx.x; i < n; i += gridDim.x * blockDim.x)
        dst[i] = ((const float4*)g_x)[i];
}

// ---------------- weight rounding ----------------
__global__ void round_kernel(const float4* __restrict__ src, float4* __restrict__ dst, int n4) {
    for (int i = blockIdx.x * blockDim.x + threadIdx.x; i < n4; i += gridDim.x * blockDim.x) {
        float4 v = src[i];
        v.x = f2tff(v.x); v.y = f2tff(v.y); v.z = f2tff(v.z); v.w = f2tff(v.w);
        dst[i] = v;
    }
}
// interleave fc1: out row 2j = gate row j, out row 2j+1 = val row (HID+j); rounded
__global__ void fc1_prep_kernel(const float* __restrict__ src) {
    int n = 2 * HID * CDIM;
    for (int o = blockIdx.x * blockDim.x + threadIdx.x; o < n; o += gridDim.x * blockDim.x) {
        int orow = o / CDIM, col = o - orow * CDIM;
        int srow = (orow >> 1) + (orow & 1) * HID;
        g_wfc1[o] = f2tff(src[(size_t)srow * CDIM + col]);
    }
}
__global__ void fc1_bias_kernel(const float* __restrict__ src) {
    int o = blockIdx.x * blockDim.x + threadIdx.x;
    if (o < 2 * HID) g_bfc1[o] = src[(o >> 1) + (o & 1) * HID];
}

// ---------------- gather: roll + window partition, rounds to tf32 ----------------
__global__ void gather_win_kernel(int shift) {
    int rw = blockIdx.x;
    int w = rw >> 6, n = rw & 63;
    int b = w >> 7, wi = w & 127;
    int wh = wi >> 4, ww = wi & 15;
    int r = n >> 3, c = n & 7;
    int sh = (wh * 8 + r + shift) & 63;
    int sw = (ww * 8 + c + shift) & 127;
    int src = (b << 13) + sh * 128 + sw;
    const float4* s = (const float4*)&g_x[(size_t)src * CDIM];
    float4* d = (float4*)&g_xw[(size_t)rw * CDIM];
    float4 v = s[threadIdx.x];
    v.x = f2tff(v.x); v.y = f2tff(v.y); v.z = f2tff(v.z); v.w = f2tff(v.w);
    d[threadIdx.x] = v;
}

__global__ void build_qkvbias_kernel(const float* __restrict__ qb, const float* __restrict__ vb) {
    int i = blockIdx.x * blockDim.x + threadIdx.x;
    if (i < QKVN)
        g_qkvbias[i] = (i < CDIM) ? qb[i] : ((i < 2 * CDIM) ? 0.0f : vb[i - 2 * CDIM]);
}

// ---------------- tf32 mma GEMM: C = A[M,K] @ B[N,K]^T + bias ----------------
// 128x128 block, BK=8, 4-stage cp.async, ldmatrix fragments. Inputs pre-rounded.
#define SPITCH 48            // bytes per 8-float smem row
#define STAGE_BYTES 12288    // A(6144) + B(6144)

__device__ __forceinline__ void mma_tf32(float* c, unsigned a0, unsigned a1, unsigned a2,
                                         unsigned a3, unsigned b0, unsigned b1) {
    asm volatile(
        "mma.sync.aligned.m16n8k8.row.col.f32.tf32.tf32.f32 "
        "{%0,%1,%2,%3}, {%4,%5,%6,%7}, {%8,%9}, {%0,%1,%2,%3};"
        : "+f"(c[0]), "+f"(c[1]), "+f"(c[2]), "+f"(c[3])
        : "r"(a0), "r"(a1), "r"(a2), "r"(a3), "r"(b0), "r"(b1));
}
__device__ __forceinline__ void ldsm4(unsigned* d, unsigned addr) {
    asm volatile("ldmatrix.sync.aligned.m8n8.x4.shared.b16 {%0,%1,%2,%3}, [%4];"
                 : "=r"(d[0]), "=r"(d[1]), "=r"(d[2]), "=r"(d[3]) : "r"(addr));
}
__device__ __forceinline__ void cpa16(unsigned saddr, const void* g) {
    asm volatile("cp.async.cg.shared.global [%0], [%1], 16;" :: "r"(saddr), "l"(g));
}

__global__ __launch_bounds__(256, 2) void gemm_mma_kernel(
    const float* __restrict__ A, const float* __restrict__ Bw,
    const float* __restrict__ bias, float* __restrict__ C,
    int M, int N, int K, int gated) {
    __shared__ __align__(128) char sm[4 * STAGE_BYTES];
    const int tid = threadIdx.x, lane = tid & 31, wid = tid >> 5;
    const int wm = wid & 3, wn = wid >> 2;
    const int m0 = blockIdx.y * 128, n0 = blockIdx.x * 128;
    const unsigned smb = (unsigned)__cvta_generic_to_shared(sm);

    // cp.async: 256 transfers of 16B per (A|B) tile, 1 each per thread
    const int ldrow = tid >> 1, ldq = tid & 1;
    const float* gA = A  + (size_t)(m0 + ldrow) * K + ldq * 4;
    const float* gB = Bw + (size_t)(n0 + ldrow) * K + ldq * 4;
    const unsigned sA = smb + ldrow * SPITCH + ldq * 16;
    const unsigned sB = sA + 6144;

    // ldmatrix addresses
    const int sub = lane >> 3, rr = lane & 7;
    unsigned aAddr[2], bAddr[4];
#pragma unroll
    for (int mf = 0; mf < 2; mf++) {
        int row = wm * 32 + mf * 16 + (sub & 1) * 8 + rr;
        aAddr[mf] = smb + row * SPITCH + (sub >> 1) * 16;
    }
#pragma unroll
    for (int p = 0; p < 4; p++) {
        int row = wn * 64 + p * 16 + (sub >> 1) * 8 + rr;
        bAddr[p] = smb + 6144 + row * SPITCH + (sub & 1) * 16;
    }

    float acc[2][8][4];
#pragma unroll
    for (int i = 0; i < 2; i++)
#pragma unroll
        for (int j = 0; j < 8; j++)
#pragma unroll
            for (int l = 0; l < 4; l++) acc[i][j][l] = 0.0f;

    const int nk = K >> 3;
    // prologue: 3 stages in flight
#pragma unroll
    for (int s = 0; s < 3; s++) {
        if (s < nk) {
            unsigned off = s * STAGE_BYTES;
            cpa16(sA + off, gA + s * 8);
            cpa16(sB + off, gB + s * 8);
        }
        asm volatile("cp.async.commit_group;");
    }

    for (int kt = 0; kt < nk; kt++) {
        asm volatile("cp.async.wait_group 2;");
        __syncthreads();
        int nxt = kt + 3;
        if (nxt < nk) {
            unsigned off = (nxt & 3) * STAGE_BYTES;
            cpa16(sA + off, gA + nxt * 8);
            cpa16(sB + off, gB + nxt * 8);
        }
        asm volatile("cp.async.commit_group;");

        unsigned soff = (kt & 3) * STAGE_BYTES;
        unsigned a[2][4], b[4][4];
        ldsm4(a[0], aAddr[0] + soff);
        ldsm4(a[1], aAddr[1] + soff);
#pragma unroll
        for (int p = 0; p < 4; p++) ldsm4(b[p], bAddr[p] + soff);
#pragma unroll
        for (int mf = 0; mf < 2; mf++)
#pragma unroll
            for (int p = 0; p < 4; p++) {
                mma_tf32(acc[mf][2 * p],     a[mf][0], a[mf][1], a[mf][2], a[mf][3], b[p][0], b[p][1]);
                mma_tf32(acc[mf][2 * p + 1], a[mf][0], a[mf][1], a[mf][2], a[mf][3], b[p][2], b[p][3]);
            }
    }

    // epilogue
    const int g = lane >> 2, tg = lane & 3;
    if (!gated) {
#pragma unroll
        for (int mf = 0; mf < 2; mf++)
#pragma unroll
            for (int nf = 0; nf < 8; nf++) {
                int r = m0 + wm * 32 + mf * 16 + g;
                int cb = n0 + wn * 64 + nf * 8 + 2 * tg;
                float b0 = bias[cb], b1 = bias[cb + 1];
                *(float2*)&C[(size_t)r * N + cb] =
                    make_float2(acc[mf][nf][0] + b0, acc[mf][nf][1] + b1);
                *(float2*)&C[(size_t)(r + 8) * N + cb] =
                    make_float2(acc[mf][nf][2] + b0, acc[mf][nf][3] + b1);
            }
    } else {
        // columns interleaved (gate, val); output width N/2, rounded for next GEMM
        int NO = N >> 1;
#pragma unroll
        for (int mf = 0; mf < 2; mf++)
#pragma unroll
            for (int nf = 0; nf < 8; nf++) {
                int r = m0 + wm * 32 + mf * 16 + g;
                int cb = n0 + wn * 64 + nf * 8 + 2 * tg;
                int j = cb >> 1;
                float bg = bias[cb], bv = bias[cb + 1];
                float g0 = acc[mf][nf][0] + bg, v0 = acc[mf][nf][1] + bv;
                float g1 = acc[mf][nf][2] + bg, v1 = acc[mf][nf][3] + bv;
                float o0 = 0.5f * g0 * (1.0f + erff(g0 * 0.70710678118654752f)) * v0;
                float o1 = 0.5f * g1 * (1.0f + erff(g1 * 0.70710678118654752f)) * v1;
                C[(size_t)r * NO + j]       = f2tff(o0);
                C[(size_t)(r + 8) * NO + j] = f2tff(o1);
            }
    }
}

// ---------------- q/k L2 normalization ----------------
__global__ void norm_qk_kernel() {
    int v = blockIdx.x * 8 + (threadIdx.x >> 5);
    int lane = threadIdx.x & 31;
    int token = v >> 4;
    int rest = v & 15;
    int hh = rest >> 1;
    int isK = rest & 1;
    float* base = &g_qkv[(size_t)token * QKVN + isK * CDIM + hh * HD];
    float x0 = base[lane], x1 = base[lane + 32], x2 = base[lane + 64];
    float s = x0 * x0 + x1 * x1 + x2 * x2;
#pragma unroll
    for (int o = 16; o; o >>= 1) s += __shfl_xor_sync(0xffffffffu, s, o);
    float inv = 1.0f / fmaxf(sqrtf(s), 1e-12f);
    base[lane] = x0 * inv; base[lane + 32] = x1 * inv; base[lane + 64] = x2 * inv;
}

// ---------------- continuous relative position bias ----------------
__device__ __forceinline__ float coordval(int a) {
    float v = (float)(a - 7) * (8.0f / 7.0f);
    float f = log2f(fabsf(v) + 1.0f) * (1.0f / 3.0f);
    return copysignf(f, v);
}
__global__ void rpb_kernel(const float* __restrict__ w1, const float* __restrict__ b1,
                           const float* __restrict__ w2) {
    __shared__ float tbl[225][8];
    int tid = threadIdx.x;
    if (tid < 225) {
        int a = tid / 15, b_ = tid % 15;
        float c0 = coordval(a), c1 = coordval(b_);
        float acc[8] = {0, 0, 0, 0, 0, 0, 0, 0};
        for (int k = 0; k < 512; k++) {
            float hid = fmaxf(c0 * w1[k * 2 + 0] + c1 * w1[k * 2 + 1] + b1[k], 0.0f);
#pragma unroll
            for (int h = 0; h < 8; h++) acc[h] += hid * w2[h * 512 + k];
        }
#pragma unroll
        for (int h = 0; h < 8; h++) tbl[tid][h] = acc[h];
    }
    __syncthreads();
    for (int e = tid; e < HEADS * NTOK * NTOK; e += 256) {
        int h = e >> 12;
        int ij = e & 4095;
        int i = ij >> 6, j = ij & 63;
        int dy = (i >> 3) - (j >> 3) + 7;
        int dx = (i & 7) - (j & 7) + 7;
        float t = tbl[dy * 15 + dx][h];
        g_rpb[e] = 16.0f / (1.0f + expf(-t));
    }
}

// ---------------- attention per (window, head); output rounded to tf32 ----------------
__global__ void attn_kernel(const float* __restrict__ logit_scale, int shift) {
    int w = blockIdx.x;
    int h = blockIdx.y;
    __shared__ float kn[64][97];
    __shared__ float at[64][65];
    int tid = threadIdx.x;

    for (int e = tid; e < 64 * HD; e += 256) {
        int j = e / HD, dd = e % HD;
        kn[j][dd] = g_qkv[(size_t)(w * 64 + j) * QKVN + CDIM + h * HD + dd];
    }
    float scale = expf(fminf(logit_scale[h], 4.605170186f));
    int wimg = w & 127;
    int wh = wimg >> 4, ww = wimg & 15;
    __syncthreads();

    for (int e = tid; e < 4096; e += 256) {
        int i = e >> 6, j = e & 63;
        const float* qrow = &g_qkv[(size_t)(w * 64 + i) * QKVN + h * HD];
        float s = 0.0f;
#pragma unroll 8
        for (int dd = 0; dd < HD; dd++) s += qrow[dd] * kn[j][dd];
        float val = scale * s + g_rpb[h * 4096 + i * 64 + j];
        if (shift) {
            int gir = wh * 8 + (i >> 3), gic = ww * 8 + (i & 7);
            int gjr = wh * 8 + (j >> 3), gjc = ww * 8 + (j & 7);
            int idi = (gir < 56 ? 0 : (gir < 60 ? 1 : 2)) * 3 + (gic < 120 ? 0 : (gic < 124 ? 1 : 2));
            int idj = (gjr < 56 ? 0 : (gjr < 60 ? 1 : 2)) * 3 + (gjc < 120 ? 0 : (gjc < 124 ? 1 : 2));
            if (idi != idj) val -= 100.0f;
        }
        at[i][j] = val;
    }
    __syncthreads();

    if (tid < 64) {
        float mx = -1e30f;
        for (int j = 0; j < 64; j++) mx = fmaxf(mx, at[tid][j]);
        float sum = 0.0f;
        for (int j = 0; j < 64; j++) { float ev = expf(at[tid][j] - mx); at[tid][j] = ev; sum += ev; }
        float inv = 1.0f / sum;
        for (int j = 0; j < 64; j++) at[tid][j] *= inv;
    }
    __syncthreads();

    for (int e = tid; e < 64 * HD; e += 256) {
        int i = e / HD, dd = e % HD;
        float s = 0.0f;
#pragma unroll 8
        for (int m = 0; m < 64; m++)
            s += at[i][m] * g_qkv[(size_t)(w * 64 + m) * QKVN + 2 * CDIM + h * HD + dd];
        g_att[(size_t)(w * 64 + i) * CDIM + h * HD + dd] = f2tff(s);
    }
}

// ---------------- LN + residual (optional rounded copy for next GEMM A) ----------------
__global__ void ln_add_kernel(const float* __restrict__ y, const float* __restrict__ g,
                              const float* __restrict__ b, int windowed, int shift,
                              int write_rounded) {
    int prow = blockIdx.x;
    int src;
    if (windowed) {
        int bb = prow >> 13;
        int p = (prow >> 7) & 63;
        int q = prow & 127;
        int i = (p - shift + 64) & 63;
        int j = (q - shift + 128) & 127;
        src = (bb * 128 + (i >> 3) * 16 + (j >> 3)) * 64 + (i & 7) * 8 + (j & 7);
    } else {
        src = prow;
    }
    int tid = threadIdx.x;
    const float* yr = &y[(size_t)src * CDIM];
    float v0 = yr[tid], v1 = yr[tid + 256], v2 = yr[tid + 512];
    __shared__ float red[256];
    red[tid] = v0 + v1 + v2;
    __syncthreads();
    for (int o = 128; o; o >>= 1) { if (tid < o) red[tid] += red[tid + o]; __syncthreads(); }
    float mu = red[0] * (1.0f / CDIM);
    __syncthreads();
    float d0 = v0 - mu, d1 = v1 - mu, d2 = v2 - mu;
    red[tid] = d0 * d0 + d1 * d1 + d2 * d2;
    __syncthreads();
    for (int o = 128; o; o >>= 1) { if (tid < o) red[tid] += red[tid + o]; __syncthreads(); }
    float rstd = rsqrtf(red[0] * (1.0f / CDIM) + 1e-5f);
    float* xr = &g_x[(size_t)prow * CDIM];
    float n0 = xr[tid]       + d0 * rstd * g[tid]       + b[tid];
    float n1 = xr[tid + 256] + d1 * rstd * g[tid + 256] + b[tid + 256];
    float n2 = xr[tid + 512] + d2 * rstd * g[tid + 512] + b[tid + 512];
    xr[tid] = n0; xr[tid + 256] = n1; xr[tid + 512] = n2;
    if (write_rounded) {
        float* rr = &g_xr[(size_t)prow * CDIM];
        rr[tid] = f2tff(n0); rr[tid + 256] = f2tff(n1); rr[tid + 512] = f2tff(n2);
    }
}

// ---------------- host launch ----------------
extern "C" void kernel_launch(void* const* d_in, const int* in_sizes, int n_in,
                              void* d_out, int out_size) {
    const float* x_in        = (const float*)d_in[0];
    const float* norm1_g     = (const float*)d_in[1];
    const float* norm1_b     = (const float*)d_in[2];
    const float* norm2_g     = (const float*)d_in[3];
    const float* norm2_b     = (const float*)d_in[4];
    const float* qkv_w       = (const float*)d_in[5];
    const float* q_bias      = (const float*)d_in[6];
    const float* v_bias      = (const float*)d_in[7];
    const float* logit_scale = (const float*)d_in[8];
    const float* cpb_w1      = (const float*)d_in[9];
    const float* cpb_b1      = (const float*)d_in[10];
    const float* cpb_w2      = (const float*)d_in[11];
    const float* proj_w      = (const float*)d_in[12];
    const float* proj_b      = (const float*)d_in[13];
    const float* fc1_w       = (const float*)d_in[14];
    const float* fc1_b       = (const float*)d_in[15];
    const float* fc2_w       = (const float*)d_in[16];
    const float* fc2_b       = (const float*)d_in[17];

    float *px, *pxr, *pxw, *pqkv, *patt, *py, *ph, *pqb;
    float *pwqkv, *pwproj, *pwfc1, *pwfc2, *pbfc1;
    cudaGetSymbolAddress((void**)&px,    g_x);
    cudaGetSymbolAddress((void**)&pxr,   g_xr);
    cudaGetSymbolAddress((void**)&pxw,   g_xw);
    cudaGetSymbolAddress((void**)&pqkv,  g_qkv);
    cudaGetSymbolAddress((void**)&patt,  g_att);
    cudaGetSymbolAddress((void**)&py,    g_y);
    cudaGetSymbolAddress((void**)&ph,    g_h);
    cudaGetSymbolAddress((void**)&pqb,   g_qkvbias);
    cudaGetSymbolAddress((void**)&pwqkv, g_wqkv);
    cudaGetSymbolAddress((void**)&pwproj,g_wproj);
    cudaGetSymbolAddress((void**)&pwfc1, g_wfc1);
    cudaGetSymbolAddress((void**)&pwfc2, g_wfc2);
    cudaGetSymbolAddress((void**)&pbfc1, g_bfc1);

    copy_in_kernel<<<4096, 256>>>((const float4*)x_in);

    for (int d = 0; d < 2; d++) {
        int shift = (d & 1) ? SHIFT : 0;

        // round weights for this depth
        round_kernel<<<2048, 256>>>((const float4*)(qkv_w + (size_t)d * QKVN * CDIM),
                                    (float4*)pwqkv, QKVN * CDIM / 4);
        round_kernel<<<2048, 256>>>((const float4*)(proj_w + (size_t)d * CDIM * CDIM),
                                    (float4*)pwproj, CDIM * CDIM / 4);
        fc1_prep_kernel<<<4096, 256>>>(fc1_w + (size_t)d * 2 * HID * CDIM);
        fc1_bias_kernel<<<24, 256>>>(fc1_b + (size_t)d * 2 * HID);
        round_kernel<<<2048, 256>>>((const float4*)(fc2_w + (size_t)d * CDIM * HID),
                                    (float4*)pwfc2, CDIM * HID / 4);

        gather_win_kernel<<<ROWS, 192>>>(shift);
        build_qkvbias_kernel<<<9, 256>>>(q_bias + d * CDIM, v_bias + d * CDIM);

        {   // qkv: 32768 x 2304 x 768
            dim3 grid(QKVN / 128, ROWS / 128);
            gemm_mma_kernel<<<grid, 256>>>(pxw, pwqkv, pqb, pqkv, ROWS, QKVN, CDIM, 0);
        }
        norm_qk_kernel<<<ROWS * 16 / 8, 256>>>();
        rpb_kernel<<<1, 256>>>(cpb_w1 + d * 512 * 2, cpb_b1 + d * 512, cpb_w2 + d * 8 * 512);

        {   // attention
            dim3 grid(WINDOWS, HEADS);
            attn_kernel<<<grid, 256>>>(logit_scale + d * HEADS, shift);
        }
        {   // proj: 32768 x 768 x 768
            dim3 grid(CDIM / 128, ROWS / 128);
            gemm_mma_kernel<<<grid, 256>>>(patt, pwproj, proj_b + d * CDIM, py,
                                           ROWS, CDIM, CDIM, 0);
        }
        ln_add_kernel<<<ROWS, 256>>>(py, norm1_g + d * CDIM, norm1_b + d * CDIM, 1, shift, 1);

        {   // fc1 gated (interleaved columns): 32768 x 6144 x 768 -> g_h [32768 x 3072]
            dim3 grid(2 * HID / 128, ROWS / 128);
            gemm_mma_kernel<<<grid, 256>>>(pxr, pwfc1, pbfc1, ph, ROWS, 2 * HID, CDIM, 1);
        }
        {   // fc2: 32768 x 768 x 3072
            dim3 grid(CDIM / 128, ROWS / 128);
            gemm_mma_kernel<<<grid, 256>>>(ph, pwfc2, fc2_b + d * CDIM, py,
                                           ROWS, CDIM, HID, 0);
        }
        ln_add_kernel<<<ROWS, 256>>>(py, norm2_g + d * CDIM, norm2_b + d * CDIM, 0, 0, 0);
    }

    copy_out_kernel<<<4096, 256>>>((float4*)d_out);
}